// round 1
// baseline (speedup 1.0000x reference)
#include <cuda_runtime.h>

// Problem dims (fixed by the dataset)
#define NTOK 4096          // b*t = 2*2048
#define DDIM 512
#define NEXP 8
#define HDIM 1024
#define H2   2048

// -------- scratch (device globals; no allocation allowed in kernel_launch) --------
__device__ int   g_cnt[NEXP];
__device__ int   g_tok[NEXP * NTOK];
__device__ float g_wt [NEXP * NTOK];
__device__ float g_act[(size_t)NEXP * NTOK * HDIM];   // ~134 MB

// =============================== zero ===============================
__global__ void k_zero(float* __restrict__ out) {
    int i = blockIdx.x * blockDim.x + threadIdx.x;
    if (i < NTOK * DDIM) out[i] = 0.f;
    if (i < NEXP) g_cnt[i] = 0;
}

// =============================== router ===============================
// one warp per token: 8 logits via warp reduction, top-2, softmax over the 2.
__global__ __launch_bounds__(256) void k_router(const float* __restrict__ x,
                                                const float* __restrict__ rw,
                                                const float* __restrict__ rb) {
    int tok  = blockIdx.x * 8 + (threadIdx.x >> 5);
    int lane = threadIdx.x & 31;
    if (tok >= NTOK) return;
    const float* xr = x + (size_t)tok * DDIM;
    float acc[NEXP];
#pragma unroll
    for (int e = 0; e < NEXP; e++) acc[e] = 0.f;
    for (int i = lane; i < DDIM; i += 32) {
        float xv = xr[i];
#pragma unroll
        for (int e = 0; e < NEXP; e++) acc[e] += xv * rw[e * DDIM + i];
    }
#pragma unroll
    for (int e = 0; e < NEXP; e++) {
#pragma unroll
        for (int o = 16; o > 0; o >>= 1)
            acc[e] += __shfl_xor_sync(0xffffffffu, acc[e], o);
    }
    if (lane == 0) {
        float lg[NEXP];
#pragma unroll
        for (int e = 0; e < NEXP; e++) lg[e] = acc[e] + rb[e];
        int i0 = 0; float v0 = lg[0];
#pragma unroll
        for (int e = 1; e < NEXP; e++) if (lg[e] > v0) { v0 = lg[e]; i0 = e; }
        int i1 = -1; float v1 = -3.0e38f;
#pragma unroll
        for (int e = 0; e < NEXP; e++) if (e != i0 && lg[e] > v1) { v1 = lg[e]; i1 = e; }
        // softmax over {v0, v1} with v0 >= v1
        float t  = __expf(v1 - v0);
        float w0 = 1.f / (1.f + t);
        float w1 = 1.f - w0;
        int s0 = atomicAdd(&g_cnt[i0], 1);
        g_tok[i0 * NTOK + s0] = tok;  g_wt[i0 * NTOK + s0] = w0;
        int s1 = atomicAdd(&g_cnt[i1], 1);
        g_tok[i1 * NTOK + s1] = tok;  g_wt[i1 * NTOK + s1] = w1;
    }
}

// =============================== fc1 + SwiGLU ===============================
// Block: 256 threads, tile = 64 tokens x (32 h1-cols + their 32 h2 partners).
// grid = (HDIM/32, NTOK/64, NEXP) with early-exit on token tile.
__global__ __launch_bounds__(256) void k_fc1(const float* __restrict__ x,
                                             const float* __restrict__ w1,
                                             const float* __restrict__ b1) {
    int e   = blockIdx.z;
    int cnt = g_cnt[e];
    int m0  = blockIdx.y * 64;
    if (m0 >= cnt) return;
    int c0  = blockIdx.x * 32;

    __shared__ float Xs[64][17];
    __shared__ float Ws[64][17];
    __shared__ int   s_tok[64];

    int tid = threadIdx.x;
    if (tid < 64) {
        int m = m0 + tid;
        s_tok[tid] = (m < cnt) ? g_tok[e * NTOK + m] : -1;
    }
    __syncthreads();

    int lrow = tid >> 2;
    int lq   = (tid & 3) * 4;
    int xrow = (s_tok[lrow] < 0) ? 0 : s_tok[lrow];
    const float* xp = x + (size_t)xrow * DDIM + lq;
    int wr = (lrow < 32) ? (c0 + lrow) : (HDIM + c0 + (lrow - 32));
    const float* wp = w1 + ((size_t)e * H2 + wr) * DDIM + lq;

    int ty = tid >> 4, tx = tid & 15;
    float acc[4][4] = {};

    for (int k0 = 0; k0 < DDIM; k0 += 16) {
        float4 xv = *(const float4*)(xp + k0);
        float4 wv = *(const float4*)(wp + k0);
        Xs[lrow][lq + 0] = xv.x; Xs[lrow][lq + 1] = xv.y;
        Xs[lrow][lq + 2] = xv.z; Xs[lrow][lq + 3] = xv.w;
        Ws[lrow][lq + 0] = wv.x; Ws[lrow][lq + 1] = wv.y;
        Ws[lrow][lq + 2] = wv.z; Ws[lrow][lq + 3] = wv.w;
        __syncthreads();
#pragma unroll
        for (int kk = 0; kk < 16; kk++) {
            float av[4], bv[4];
#pragma unroll
            for (int i = 0; i < 4; i++) av[i] = Xs[ty + 16 * i][kk];
#pragma unroll
            for (int j = 0; j < 4; j++) bv[j] = Ws[tx + 16 * j][kk];
#pragma unroll
            for (int i = 0; i < 4; i++)
#pragma unroll
                for (int j = 0; j < 4; j++) acc[i][j] += av[i] * bv[j];
        }
        __syncthreads();
    }

#pragma unroll
    for (int i = 0; i < 4; i++) {
        int r = ty + 16 * i;
        int m = m0 + r;
        if (m >= cnt) continue;
        size_t abase = ((size_t)e * NTOK + m) * HDIM + c0;
#pragma unroll
        for (int j = 0; j < 2; j++) {
            int lc = tx + 16 * j;                       // local col within [0,32)
            float h1 = acc[i][j]     + b1[e * H2 + c0 + lc];
            float h2 = acc[i][j + 2] + b1[e * H2 + HDIM + c0 + lc];
            float s  = h1 / (1.f + __expf(-h1));        // silu
            g_act[abase + lc] = s * h2;
        }
    }
}

// =============================== fc2 + weighted combine ===============================
// Block: 256 threads, tile = 64 tokens x 64 d-outputs, K = HDIM.
// grid = (DDIM/64, NTOK/64, NEXP)
__global__ __launch_bounds__(256) void k_fc2(const float* __restrict__ w2,
                                             const float* __restrict__ b2,
                                             float* __restrict__ out) {
    int e   = blockIdx.z;
    int cnt = g_cnt[e];
    int m0  = blockIdx.y * 64;
    if (m0 >= cnt) return;
    int n0  = blockIdx.x * 64;

    __shared__ float As[64][17];
    __shared__ float Ws[64][17];
    __shared__ int   s_tok[64];
    __shared__ float s_wt[64];

    int tid = threadIdx.x;
    if (tid < 64) {
        int m = m0 + tid;
        if (m < cnt) { s_tok[tid] = g_tok[e * NTOK + m]; s_wt[tid] = g_wt[e * NTOK + m]; }
        else         { s_tok[tid] = -1;                  s_wt[tid] = 0.f; }
    }
    __syncthreads();

    int lrow = tid >> 2;
    int lq   = (tid & 3) * 4;
    const float* ap = g_act + ((size_t)e * NTOK + m0 + lrow) * HDIM + lq;
    const float* wp = w2 + ((size_t)e * DDIM + n0 + lrow) * HDIM + lq;

    int ty = tid >> 4, tx = tid & 15;
    float acc[4][4] = {};

    for (int k0 = 0; k0 < HDIM; k0 += 16) {
        float4 av4 = *(const float4*)(ap + k0);
        float4 wv4 = *(const float4*)(wp + k0);
        As[lrow][lq + 0] = av4.x; As[lrow][lq + 1] = av4.y;
        As[lrow][lq + 2] = av4.z; As[lrow][lq + 3] = av4.w;
        Ws[lrow][lq + 0] = wv4.x; Ws[lrow][lq + 1] = wv4.y;
        Ws[lrow][lq + 2] = wv4.z; Ws[lrow][lq + 3] = wv4.w;
        __syncthreads();
#pragma unroll
        for (int kk = 0; kk < 16; kk++) {
            float av[4], bv[4];
#pragma unroll
            for (int i = 0; i < 4; i++) av[i] = As[ty + 16 * i][kk];
#pragma unroll
            for (int j = 0; j < 4; j++) bv[j] = Ws[tx + 16 * j][kk];
#pragma unroll
            for (int i = 0; i < 4; i++)
#pragma unroll
                for (int j = 0; j < 4; j++) acc[i][j] += av[i] * bv[j];
        }
        __syncthreads();
    }

#pragma unroll
    for (int i = 0; i < 4; i++) {
        int r = ty + 16 * i;
        int m = m0 + r;
        if (m >= cnt) continue;
        int   tok = s_tok[r];
        float w   = s_wt[r];
#pragma unroll
        for (int j = 0; j < 4; j++) {
            int n = n0 + tx + 16 * j;
            float v = (acc[i][j] + b2[e * DDIM + n]) * w;
            atomicAdd(&out[(size_t)tok * DDIM + n], v);
        }
    }
}

// =============================== launch ===============================
extern "C" void kernel_launch(void* const* d_in, const int* in_sizes, int n_in,
                              void* d_out, int out_size) {
    const float* x   = (const float*)d_in[0];
    const float* rw  = (const float*)d_in[1];
    const float* rb  = (const float*)d_in[2];
    const float* f1w = (const float*)d_in[3];
    const float* f1b = (const float*)d_in[4];
    const float* f2w = (const float*)d_in[5];
    const float* f2b = (const float*)d_in[6];
    float* out = (float*)d_out;

    k_zero<<<(NTOK * DDIM + 255) / 256, 256>>>(out);
    k_router<<<NTOK / 8, 256>>>(x, rw, rb);
    k_fc1<<<dim3(HDIM / 32, NTOK / 64, NEXP), 256>>>(x, f1w, f1b);
    k_fc2<<<dim3(DDIM / 64, NTOK / 64, NEXP), 256>>>(f2w, f2b, out);
}

// round 3
// speedup vs baseline: 2.5216x; 2.5216x over previous
#include <cuda_runtime.h>
#include <cstdint>

#define NTOK 4096
#define DDIM 512
#define NEXP 8
#define HDIM 1024
#define H2   2048

// smem strides (floats), padded to dodge bank conflicts
#define AS 20
#define NC1 (DDIM / 16)    // 32 chunks for fc1
#define NC2 (HDIM / 16)    // 64 chunks for fc2

// -------- scratch --------
__device__ int   g_cnt[NEXP];
__device__ int   g_tok[NEXP * NTOK];
__device__ float g_wt [NEXP * NTOK];
__device__ float g_act[(size_t)NEXP * NTOK * HDIM];

// ===================== helpers =====================
__device__ __forceinline__ uint32_t tf32r(float f) {
    uint32_t u; asm("cvt.rna.tf32.f32 %0, %1;" : "=r"(u) : "f"(f)); return u;
}
__device__ __forceinline__ void st_tf32x4(float* dst, float4 v) {
    uint4 u = make_uint4(tf32r(v.x), tf32r(v.y), tf32r(v.z), tf32r(v.w));
    *(uint4*)dst = u;
}
__device__ __forceinline__ void mma_tf32(float* c, const uint32_t* a, uint32_t b0, uint32_t b1) {
    asm volatile(
        "mma.sync.aligned.m16n8k8.row.col.f32.tf32.tf32.f32 "
        "{%0,%1,%2,%3}, {%4,%5,%6,%7}, {%8,%9}, {%0,%1,%2,%3};"
        : "+f"(c[0]), "+f"(c[1]), "+f"(c[2]), "+f"(c[3])
        : "r"(a[0]), "r"(a[1]), "r"(a[2]), "r"(a[3]), "r"(b0), "r"(b1));
}

// =============================== zero ===============================
__global__ void k_zero(float* __restrict__ out) {
    int i = blockIdx.x * blockDim.x + threadIdx.x;
    if (i < NTOK * DDIM) out[i] = 0.f;
    if (i < NEXP) g_cnt[i] = 0;
}

// =============================== router (fp32 exact) ===============================
__global__ __launch_bounds__(256) void k_router(const float* __restrict__ x,
                                                const float* __restrict__ rw,
                                                const float* __restrict__ rb) {
    int tok  = blockIdx.x * 8 + (threadIdx.x >> 5);
    int lane = threadIdx.x & 31;
    if (tok >= NTOK) return;
    const float* xr = x + (size_t)tok * DDIM;
    float acc[NEXP];
#pragma unroll
    for (int e = 0; e < NEXP; e++) acc[e] = 0.f;
    for (int i = lane; i < DDIM; i += 32) {
        float xv = xr[i];
#pragma unroll
        for (int e = 0; e < NEXP; e++) acc[e] += xv * rw[e * DDIM + i];
    }
#pragma unroll
    for (int e = 0; e < NEXP; e++) {
#pragma unroll
        for (int o = 16; o > 0; o >>= 1)
            acc[e] += __shfl_xor_sync(0xffffffffu, acc[e], o);
    }
    if (lane == 0) {
        float lg[NEXP];
#pragma unroll
        for (int e = 0; e < NEXP; e++) lg[e] = acc[e] + rb[e];
        int i0 = 0; float v0 = lg[0];
#pragma unroll
        for (int e = 1; e < NEXP; e++) if (lg[e] > v0) { v0 = lg[e]; i0 = e; }
        int i1 = -1; float v1 = -3.0e38f;
#pragma unroll
        for (int e = 0; e < NEXP; e++) if (e != i0 && lg[e] > v1) { v1 = lg[e]; i1 = e; }
        float t  = __expf(v1 - v0);
        float w0 = 1.f / (1.f + t);
        float w1 = 1.f - w0;
        int s0 = atomicAdd(&g_cnt[i0], 1);
        g_tok[i0 * NTOK + s0] = tok;  g_wt[i0 * NTOK + s0] = w0;
        int s1 = atomicAdd(&g_cnt[i1], 1);
        g_tok[i1 * NTOK + s1] = tok;  g_wt[i1 * NTOK + s1] = w1;
    }
}

// =============================== fc1: mma.sync tf32 + SwiGLU ===============================
// Block tile: 128 tokens x 64 cols (= 32 h1/h2 pairs, rows interleaved even=h1 odd=h2).
// 256 threads = 8 warps (4m x 2n), warp tile 32x32. grid = (HDIM/32, NTOK/128, NEXP).
__global__ __launch_bounds__(256) void k_fc1(const float* __restrict__ x,
                                             const float* __restrict__ w1,
                                             const float* __restrict__ b1) {
    int e   = blockIdx.z;
    int cnt = g_cnt[e];
    int m0  = blockIdx.y * 128;
    if (m0 >= cnt) return;
    int c0  = blockIdx.x * 32;   // pair base

    __shared__ float Asm[2 * 128 * AS];
    __shared__ float Bsm[2 * 64 * AS];
    __shared__ int s_tok[128];

    int tid = threadIdx.x, wid = tid >> 5, lane = tid & 31;
    if (tid < 128) {
        int m = m0 + tid;
        s_tok[tid] = (m < cnt) ? g_tok[e * NTOK + m] : 0;
    }
    __syncthreads();

    // staging assignment: A: 2 float4/thread, B: 1 float4/thread
    int arow = tid >> 1, aq = (tid & 1) * 8;
    const float* ap = x + (size_t)s_tok[arow] * DDIM + aq;
    float* a_st = Asm + arow * AS + aq;
    int brow = tid >> 2, bq = (tid & 3) * 4;
    int pj   = brow >> 1;
    int w1row = (brow & 1) ? (HDIM + c0 + pj) : (c0 + pj);
    const float* bp = w1 + ((size_t)e * H2 + w1row) * DDIM + bq;
    float* b_st = Bsm + brow * AS + bq;

    int wm = (wid >> 1) * 32;
    int wn = (wid & 1) * 32;
    float acc[2][4][4] = {};

    // prologue
    float4 av0 = *(const float4*)(ap), av1 = *(const float4*)(ap + 4);
    float4 bv0 = *(const float4*)(bp);
    st_tf32x4(a_st, av0); st_tf32x4(a_st + 4, av1);
    st_tf32x4(b_st, bv0);
    __syncthreads();

    for (int c = 0; c < NC1; c++) {
        int s = c & 1;
        if (c + 1 < NC1) {
            int k0 = (c + 1) * 16;
            av0 = *(const float4*)(ap + k0); av1 = *(const float4*)(ap + k0 + 4);
            bv0 = *(const float4*)(bp + k0);
        }
        const float* A = Asm + s * 128 * AS;
        const float* B = Bsm + s * 64 * AS;
#pragma unroll
        for (int k8 = 0; k8 < 2; k8++) {
            int kc = k8 * 8 + (lane & 3);
            uint32_t a[2][4];
#pragma unroll
            for (int mt = 0; mt < 2; mt++) {
                int r = wm + mt * 16 + (lane >> 2);
                a[mt][0] = __float_as_uint(A[r * AS + kc]);
                a[mt][1] = __float_as_uint(A[(r + 8) * AS + kc]);
                a[mt][2] = __float_as_uint(A[r * AS + kc + 4]);
                a[mt][3] = __float_as_uint(A[(r + 8) * AS + kc + 4]);
            }
#pragma unroll
            for (int nt = 0; nt < 4; nt++) {
                int rn = wn + nt * 8 + (lane >> 2);
                uint32_t b0 = __float_as_uint(B[rn * AS + kc]);
                uint32_t b1r = __float_as_uint(B[rn * AS + kc + 4]);
                mma_tf32(acc[0][nt], a[0], b0, b1r);
                mma_tf32(acc[1][nt], a[1], b0, b1r);
            }
        }
        if (c + 1 < NC1) {
            int s2 = (c + 1) & 1;
            st_tf32x4(Asm + s2 * 128 * AS + arow * AS + aq, av0);
            st_tf32x4(Asm + s2 * 128 * AS + arow * AS + aq + 4, av1);
            st_tf32x4(Bsm + s2 * 64 * AS + brow * AS + bq, bv0);
        }
        __syncthreads();
    }

    // epilogue: c0/c1 of each accumulator = (h1,h2) SwiGLU pair
    const float* bb = b1 + (size_t)e * H2;
#pragma unroll
    for (int mt = 0; mt < 2; mt++) {
        int r_lo = m0 + wm + mt * 16 + (lane >> 2);
#pragma unroll
        for (int nt = 0; nt < 4; nt++) {
            int hcol = c0 + (wn >> 1) + nt * 4 + (lane & 3);
            float bh1 = bb[hcol];
            float bh2 = bb[HDIM + hcol];
            if (r_lo < cnt) {
                float h1 = acc[mt][nt][0] + bh1;
                float h2 = acc[mt][nt][1] + bh2;
                g_act[((size_t)e * NTOK + r_lo) * HDIM + hcol] =
                    (h1 / (1.f + __expf(-h1))) * h2;
            }
            int r_hi = r_lo + 8;
            if (r_hi < cnt) {
                float h1 = acc[mt][nt][2] + bh1;
                float h2 = acc[mt][nt][3] + bh2;
                g_act[((size_t)e * NTOK + r_hi) * HDIM + hcol] =
                    (h1 / (1.f + __expf(-h1))) * h2;
            }
        }
    }
}

// =============================== fc2: mma.sync tf32 + weighted combine ===============================
// Block tile: 128 tokens x 64 d-outputs. grid = (DDIM/64, NTOK/128, NEXP).
__global__ __launch_bounds__(256) void k_fc2(const float* __restrict__ w2,
                                             const float* __restrict__ b2,
                                             float* __restrict__ out) {
    int e   = blockIdx.z;
    int cnt = g_cnt[e];
    int m0  = blockIdx.y * 128;
    if (m0 >= cnt) return;
    int n0  = blockIdx.x * 64;

    __shared__ float Asm[2 * 128 * AS];
    __shared__ float Bsm[2 * 64 * AS];
    __shared__ int   s_tok[128];
    __shared__ float s_wt[128];

    int tid = threadIdx.x, wid = tid >> 5, lane = tid & 31;
    if (tid < 128) {
        int m = m0 + tid;
        if (m < cnt) { s_tok[tid] = g_tok[e * NTOK + m]; s_wt[tid] = g_wt[e * NTOK + m]; }
        else         { s_tok[tid] = 0;                   s_wt[tid] = 0.f; }
    }
    __syncthreads();

    int arow = tid >> 1, aq = (tid & 1) * 8;
    const float* ap = g_act + ((size_t)e * NTOK + m0 + arow) * HDIM + aq;
    float* a_st = Asm + arow * AS + aq;
    int brow = tid >> 2, bq = (tid & 3) * 4;
    const float* bp = w2 + ((size_t)e * DDIM + n0 + brow) * HDIM + bq;
    float* b_st = Bsm + brow * AS + bq;

    int wm = (wid >> 1) * 32;
    int wn = (wid & 1) * 32;
    float acc[2][4][4] = {};

    float4 av0 = *(const float4*)(ap), av1 = *(const float4*)(ap + 4);
    float4 bv0 = *(const float4*)(bp);
    st_tf32x4(a_st, av0); st_tf32x4(a_st + 4, av1);
    st_tf32x4(b_st, bv0);
    __syncthreads();

    for (int c = 0; c < NC2; c++) {
        int s = c & 1;
        if (c + 1 < NC2) {
            int k0 = (c + 1) * 16;
            av0 = *(const float4*)(ap + k0); av1 = *(const float4*)(ap + k0 + 4);
            bv0 = *(const float4*)(bp + k0);
        }
        const float* A = Asm + s * 128 * AS;
        const float* B = Bsm + s * 64 * AS;
#pragma unroll
        for (int k8 = 0; k8 < 2; k8++) {
            int kc = k8 * 8 + (lane & 3);
            uint32_t a[2][4];
#pragma unroll
            for (int mt = 0; mt < 2; mt++) {
                int r = wm + mt * 16 + (lane >> 2);
                a[mt][0] = __float_as_uint(A[r * AS + kc]);
                a[mt][1] = __float_as_uint(A[(r + 8) * AS + kc]);
                a[mt][2] = __float_as_uint(A[r * AS + kc + 4]);
                a[mt][3] = __float_as_uint(A[(r + 8) * AS + kc + 4]);
            }
#pragma unroll
            for (int nt = 0; nt < 4; nt++) {
                int rn = wn + nt * 8 + (lane >> 2);
                uint32_t b0 = __float_as_uint(B[rn * AS + kc]);
                uint32_t b1r = __float_as_uint(B[rn * AS + kc + 4]);
                mma_tf32(acc[0][nt], a[0], b0, b1r);
                mma_tf32(acc[1][nt], a[1], b0, b1r);
            }
        }
        if (c + 1 < NC2) {
            int s2 = (c + 1) & 1;
            st_tf32x4(Asm + s2 * 128 * AS + arow * AS + aq, av0);
            st_tf32x4(Asm + s2 * 128 * AS + arow * AS + aq + 4, av1);
            st_tf32x4(Bsm + s2 * 64 * AS + brow * AS + bq, bv0);
        }
        __syncthreads();
    }

    const float* bb = b2 + (size_t)e * DDIM;
#pragma unroll
    for (int mt = 0; mt < 2; mt++) {
        int r_lo = wm + mt * 16 + (lane >> 2);
#pragma unroll
        for (int nt = 0; nt < 4; nt++) {
            int n_e = n0 + wn + nt * 8 + 2 * (lane & 3);
            float be = bb[n_e], bo = bb[n_e + 1];
            if (m0 + r_lo < cnt) {
                int tok = s_tok[r_lo]; float wt = s_wt[r_lo];
                atomicAdd(&out[(size_t)tok * DDIM + n_e],     (acc[mt][nt][0] + be) * wt);
                atomicAdd(&out[(size_t)tok * DDIM + n_e + 1], (acc[mt][nt][1] + bo) * wt);
            }
            int r_hi = r_lo + 8;
            if (m0 + r_hi < cnt) {
                int tok = s_tok[r_hi]; float wt = s_wt[r_hi];
                atomicAdd(&out[(size_t)tok * DDIM + n_e],     (acc[mt][nt][2] + be) * wt);
                atomicAdd(&out[(size_t)tok * DDIM + n_e + 1], (acc[mt][nt][3] + bo) * wt);
            }
        }
    }
}

// =============================== launch ===============================
extern "C" void kernel_launch(void* const* d_in, const int* in_sizes, int n_in,
                              void* d_out, int out_size) {
    const float* x   = (const float*)d_in[0];
    const float* rw  = (const float*)d_in[1];
    const float* rb  = (const float*)d_in[2];
    const float* f1w = (const float*)d_in[3];
    const float* f1b = (const float*)d_in[4];
    const float* f2w = (const float*)d_in[5];
    const float* f2b = (const float*)d_in[6];
    float* out = (float*)d_out;

    k_zero<<<(NTOK * DDIM + 255) / 256, 256>>>(out);
    k_router<<<NTOK / 8, 256>>>(x, rw, rb);
    k_fc1<<<dim3(HDIM / 32, NTOK / 128, NEXP), 256>>>(x, f1w, f1b);
    k_fc2<<<dim3(DDIM / 64, NTOK / 128, NEXP), 256>>>(f2w, f2b, out);
}

// round 4
// speedup vs baseline: 2.8907x; 1.1464x over previous
#include <cuda_runtime.h>
#include <cstdint>

#define NTOK 4096
#define DDIM 512
#define NEXP 8
#define HDIM 1024
#define H2   2048

#define AS 20              // smem row stride (floats), conflict-free for our patterns
#define NC1 (DDIM / 16)    // 32 K-chunks for fc1
#define NC2 (HDIM / 16)    // 64 K-chunks for fc2

// -------- scratch --------
__device__ int   g_cnt[NEXP];
__device__ int   g_tok[NEXP * NTOK];
__device__ float g_wt [NEXP * NTOK];
__device__ float g_act[(size_t)NEXP * NTOK * HDIM];

// ===================== helpers =====================
__device__ __forceinline__ uint32_t tf32r(float f) {
    uint32_t u; asm("cvt.rna.tf32.f32 %0, %1;" : "=r"(u) : "f"(f)); return u;
}
__device__ __forceinline__ void st_tf32x4(float* dst, float4 v) {
    uint4 u = make_uint4(tf32r(v.x), tf32r(v.y), tf32r(v.z), tf32r(v.w));
    *(uint4*)dst = u;
}
__device__ __forceinline__ void mma_tf32(float* c, const uint32_t* a, uint32_t b0, uint32_t b1) {
    asm volatile(
        "mma.sync.aligned.m16n8k8.row.col.f32.tf32.tf32.f32 "
        "{%0,%1,%2,%3}, {%4,%5,%6,%7}, {%8,%9}, {%0,%1,%2,%3};"
        : "+f"(c[0]), "+f"(c[1]), "+f"(c[2]), "+f"(c[3])
        : "r"(a[0]), "r"(a[1]), "r"(a[2]), "r"(a[3]), "r"(b0), "r"(b1));
}

// =============================== zero ===============================
__global__ void k_zero(float* __restrict__ out) {
    int i = blockIdx.x * blockDim.x + threadIdx.x;
    if (i < NTOK * DDIM) out[i] = 0.f;
    if (i < NEXP) g_cnt[i] = 0;
}

// =============================== router (fp32 exact) ===============================
__global__ __launch_bounds__(256) void k_router(const float* __restrict__ x,
                                                const float* __restrict__ rw,
                                                const float* __restrict__ rb) {
    int tok  = blockIdx.x * 8 + (threadIdx.x >> 5);
    int lane = threadIdx.x & 31;
    if (tok >= NTOK) return;
    const float* xr = x + (size_t)tok * DDIM;
    float acc[NEXP];
#pragma unroll
    for (int e = 0; e < NEXP; e++) acc[e] = 0.f;
    for (int i = lane; i < DDIM; i += 32) {
        float xv = xr[i];
#pragma unroll
        for (int e = 0; e < NEXP; e++) acc[e] += xv * rw[e * DDIM + i];
    }
#pragma unroll
    for (int e = 0; e < NEXP; e++) {
#pragma unroll
        for (int o = 16; o > 0; o >>= 1)
            acc[e] += __shfl_xor_sync(0xffffffffu, acc[e], o);
    }
    if (lane == 0) {
        float lg[NEXP];
#pragma unroll
        for (int e = 0; e < NEXP; e++) lg[e] = acc[e] + rb[e];
        int i0 = 0; float v0 = lg[0];
#pragma unroll
        for (int e = 1; e < NEXP; e++) if (lg[e] > v0) { v0 = lg[e]; i0 = e; }
        int i1 = -1; float v1 = -3.0e38f;
#pragma unroll
        for (int e = 0; e < NEXP; e++) if (e != i0 && lg[e] > v1) { v1 = lg[e]; i1 = e; }
        float t  = __expf(v1 - v0);
        float w0 = 1.f / (1.f + t);
        float w1 = 1.f - w0;
        int s0 = atomicAdd(&g_cnt[i0], 1);
        g_tok[i0 * NTOK + s0] = tok;  g_wt[i0 * NTOK + s0] = w0;
        int s1 = atomicAdd(&g_cnt[i1], 1);
        g_tok[i1 * NTOK + s1] = tok;  g_wt[i1 * NTOK + s1] = w1;
    }
}

// ======= shared GEMM inner step: 8 warps (4m x 2n), warp tile 32x64, chunk K=16 =======
// A: [128][16] tf32 in smem (stride AS), B: [128][16] tf32 in smem (stride AS).
// acc[2][8][4]: mt in {0,1} (rows wm+mt*16+..), nt in {0..7} (cols wn+nt*8+..).
#define GEMM_CHUNK(A, B, wm, wn, lane, acc)                                   \
    _Pragma("unroll")                                                          \
    for (int k8 = 0; k8 < 2; k8++) {                                           \
        int kc = k8 * 8 + ((lane) & 3);                                        \
        uint32_t afr[2][4];                                                    \
        _Pragma("unroll")                                                      \
        for (int mt = 0; mt < 2; mt++) {                                       \
            int r = (wm) + mt * 16 + ((lane) >> 2);                            \
            afr[mt][0] = __float_as_uint((A)[r * AS + kc]);                    \
            afr[mt][1] = __float_as_uint((A)[(r + 8) * AS + kc]);              \
            afr[mt][2] = __float_as_uint((A)[r * AS + kc + 4]);                \
            afr[mt][3] = __float_as_uint((A)[(r + 8) * AS + kc + 4]);          \
        }                                                                      \
        uint32_t bfr[8][2];                                                    \
        _Pragma("unroll")                                                      \
        for (int nt = 0; nt < 8; nt++) {                                       \
            int rn = (wn) + nt * 8 + ((lane) >> 2);                            \
            bfr[nt][0] = __float_as_uint((B)[rn * AS + kc]);                   \
            bfr[nt][1] = __float_as_uint((B)[rn * AS + kc + 4]);               \
        }                                                                      \
        _Pragma("unroll")                                                      \
        for (int nt = 0; nt < 8; nt++) {                                       \
            mma_tf32(acc[0][nt], afr[0], bfr[nt][0], bfr[nt][1]);              \
            mma_tf32(acc[1][nt], afr[1], bfr[nt][0], bfr[nt][1]);              \
        }                                                                      \
    }

// =============================== fc1: tf32 mma + SwiGLU ===============================
// Block tile: 128 tokens x 128 cols (64 h1/h2 pairs interleaved: even=h1, odd=h2).
// grid = (HDIM/64, NTOK/128, NEXP), 256 threads.
__global__ __launch_bounds__(256) void k_fc1(const float* __restrict__ x,
                                             const float* __restrict__ w1,
                                             const float* __restrict__ b1) {
    int e   = blockIdx.z;
    int cnt = g_cnt[e];
    int m0  = blockIdx.y * 128;
    if (m0 >= cnt) return;
    int c0  = blockIdx.x * 64;   // pair base

    __shared__ float Asm[2 * 128 * AS];
    __shared__ float Bsm[2 * 128 * AS];
    __shared__ int s_tok[128];

    int tid = threadIdx.x, wid = tid >> 5, lane = tid & 31;
    if (tid < 128) {
        int m = m0 + tid;
        s_tok[tid] = (m < cnt) ? g_tok[e * NTOK + m] : 0;
    }
    __syncthreads();

    // staging: A and B each 128x16 floats = 512 float4; 256 thr -> 2 float4 each
    int arow = tid >> 1, aq = (tid & 1) * 8;
    const float* ap = x + (size_t)s_tok[arow] * DDIM + aq;
    float* a_st = Asm + arow * AS + aq;
    int brow = tid >> 1, bq = (tid & 1) * 8;
    int pj   = brow >> 1;
    int w1row = (brow & 1) ? (HDIM + c0 + pj) : (c0 + pj);
    const float* bp = w1 + ((size_t)e * H2 + w1row) * DDIM + bq;
    float* b_st = Bsm + brow * AS + bq;

    int wm = (wid >> 1) * 32;
    int wn = (wid & 1) * 64;
    float acc[2][8][4] = {};

    float4 av0 = *(const float4*)(ap), av1 = *(const float4*)(ap + 4);
    float4 bv0 = *(const float4*)(bp), bv1 = *(const float4*)(bp + 4);
    st_tf32x4(a_st, av0); st_tf32x4(a_st + 4, av1);
    st_tf32x4(b_st, bv0); st_tf32x4(b_st + 4, bv1);
    __syncthreads();

    for (int c = 0; c < NC1; c++) {
        int s = c & 1;
        if (c + 1 < NC1) {
            int k0 = (c + 1) * 16;
            av0 = *(const float4*)(ap + k0); av1 = *(const float4*)(ap + k0 + 4);
            bv0 = *(const float4*)(bp + k0); bv1 = *(const float4*)(bp + k0 + 4);
        }
        const float* A = Asm + s * 128 * AS;
        const float* B = Bsm + s * 128 * AS;
        GEMM_CHUNK(A, B, wm, wn, lane, acc)
        if (c + 1 < NC1) {
            int s2 = (c + 1) & 1;
            st_tf32x4(Asm + s2 * 128 * AS + arow * AS + aq, av0);
            st_tf32x4(Asm + s2 * 128 * AS + arow * AS + aq + 4, av1);
            st_tf32x4(Bsm + s2 * 128 * AS + brow * AS + bq, bv0);
            st_tf32x4(Bsm + s2 * 128 * AS + brow * AS + bq + 4, bv1);
        }
        __syncthreads();
    }

    // epilogue: acc cols come in (even,odd) = (h1,h2) pairs
    const float* bb = b1 + (size_t)e * H2;
#pragma unroll
    for (int mt = 0; mt < 2; mt++) {
        int r_lo = m0 + wm + mt * 16 + (lane >> 2);
#pragma unroll
        for (int nt = 0; nt < 8; nt++) {
            int p = (wn >> 1) + nt * 4 + (lane & 3);   // pair index within 64
            int hcol = c0 + p;
            float bh1 = bb[hcol];
            float bh2 = bb[HDIM + hcol];
            if (r_lo < cnt) {
                float h1 = acc[mt][nt][0] + bh1;
                float h2 = acc[mt][nt][1] + bh2;
                g_act[((size_t)e * NTOK + r_lo) * HDIM + hcol] =
                    (h1 / (1.f + __expf(-h1))) * h2;
            }
            int r_hi = r_lo + 8;
            if (r_hi < cnt) {
                float h1 = acc[mt][nt][2] + bh1;
                float h2 = acc[mt][nt][3] + bh2;
                g_act[((size_t)e * NTOK + r_hi) * HDIM + hcol] =
                    (h1 / (1.f + __expf(-h1))) * h2;
            }
        }
    }
}

// =============================== fc2: tf32 mma + weighted combine ===============================
// Block tile: 128 tokens x 128 d-outputs. grid = (DDIM/128, NTOK/128, NEXP).
__global__ __launch_bounds__(256) void k_fc2(const float* __restrict__ w2,
                                             const float* __restrict__ b2,
                                             float* __restrict__ out) {
    int e   = blockIdx.z;
    int cnt = g_cnt[e];
    int m0  = blockIdx.y * 128;
    if (m0 >= cnt) return;
    int n0  = blockIdx.x * 128;

    __shared__ float Asm[2 * 128 * AS];
    __shared__ float Bsm[2 * 128 * AS];
    __shared__ int   s_tok[128];
    __shared__ float s_wt[128];

    int tid = threadIdx.x, wid = tid >> 5, lane = tid & 31;
    if (tid < 128) {
        int m = m0 + tid;
        if (m < cnt) { s_tok[tid] = g_tok[e * NTOK + m]; s_wt[tid] = g_wt[e * NTOK + m]; }
        else         { s_tok[tid] = 0;                   s_wt[tid] = 0.f; }
    }
    __syncthreads();

    int arow = tid >> 1, aq = (tid & 1) * 8;
    const float* ap = g_act + ((size_t)e * NTOK + m0 + arow) * HDIM + aq;
    float* a_st = Asm + arow * AS + aq;
    int brow = tid >> 1, bq = (tid & 1) * 8;
    const float* bp = w2 + ((size_t)e * DDIM + n0 + brow) * HDIM + bq;
    float* b_st = Bsm + brow * AS + bq;

    int wm = (wid >> 1) * 32;
    int wn = (wid & 1) * 64;
    float acc[2][8][4] = {};

    float4 av0 = *(const float4*)(ap), av1 = *(const float4*)(ap + 4);
    float4 bv0 = *(const float4*)(bp), bv1 = *(const float4*)(bp + 4);
    st_tf32x4(a_st, av0); st_tf32x4(a_st + 4, av1);
    st_tf32x4(b_st, bv0); st_tf32x4(b_st + 4, bv1);
    __syncthreads();

    for (int c = 0; c < NC2; c++) {
        int s = c & 1;
        if (c + 1 < NC2) {
            int k0 = (c + 1) * 16;
            av0 = *(const float4*)(ap + k0); av1 = *(const float4*)(ap + k0 + 4);
            bv0 = *(const float4*)(bp + k0); bv1 = *(const float4*)(bp + k0 + 4);
        }
        const float* A = Asm + s * 128 * AS;
        const float* B = Bsm + s * 128 * AS;
        GEMM_CHUNK(A, B, wm, wn, lane, acc)
        if (c + 1 < NC2) {
            int s2 = (c + 1) & 1;
            st_tf32x4(Asm + s2 * 128 * AS + arow * AS + aq, av0);
            st_tf32x4(Asm + s2 * 128 * AS + arow * AS + aq + 4, av1);
            st_tf32x4(Bsm + s2 * 128 * AS + brow * AS + bq, bv0);
            st_tf32x4(Bsm + s2 * 128 * AS + brow * AS + bq + 4, bv1);
        }
        __syncthreads();
    }

    const float* bb = b2 + (size_t)e * DDIM;
#pragma unroll
    for (int mt = 0; mt < 2; mt++) {
        int r_lo = wm + mt * 16 + (lane >> 2);
#pragma unroll
        for (int nt = 0; nt < 8; nt++) {
            int n_e = n0 + wn + nt * 8 + 2 * (lane & 3);
            float be = bb[n_e - n0 + wn >= 0 ? (n_e - (size_t)0) - (size_t)e * 0 - n_e + n_e : 0]; // placeholder avoided below
            be = bb[n_e];
            float bo = bb[n_e + 1];
            if (m0 + r_lo < cnt) {
                int tok = s_tok[r_lo]; float wt = s_wt[r_lo];
                atomicAdd(&out[(size_t)tok * DDIM + n_e],     (acc[mt][nt][0] + be) * wt);
                atomicAdd(&out[(size_t)tok * DDIM + n_e + 1], (acc[mt][nt][1] + bo) * wt);
            }
            int r_hi = r_lo + 8;
            if (m0 + r_hi < cnt) {
                int tok = s_tok[r_hi]; float wt = s_wt[r_hi];
                atomicAdd(&out[(size_t)tok * DDIM + n_e],     (acc[mt][nt][2] + be) * wt);
                atomicAdd(&out[(size_t)tok * DDIM + n_e + 1], (acc[mt][nt][3] + bo) * wt);
            }
        }
    }
}

// =============================== launch ===============================
extern "C" void kernel_launch(void* const* d_in, const int* in_sizes, int n_in,
                              void* d_out, int out_size) {
    const float* x   = (const float*)d_in[0];
    const float* rw  = (const float*)d_in[1];
    const float* rb  = (const float*)d_in[2];
    const float* f1w = (const float*)d_in[3];
    const float* f1b = (const float*)d_in[4];
    const float* f2w = (const float*)d_in[5];
    const float* f2b = (const float*)d_in[6];
    float* out = (float*)d_out;

    k_zero<<<(NTOK * DDIM + 255) / 256, 256>>>(out);
    k_router<<<NTOK / 8, 256>>>(x, rw, rb);
    k_fc1<<<dim3(HDIM / 64, NTOK / 128, NEXP), 256>>>(x, f1w, f1b);
    k_fc2<<<dim3(DDIM / 128, NTOK / 128, NEXP), 256>>>(f2w, f2b, out);
}

// round 5
// speedup vs baseline: 4.1417x; 1.4327x over previous
#include <cuda_runtime.h>
#include <cuda_fp16.h>
#include <cstdint>

#define NTOK 4096
#define DDIM 512
#define NEXP 8
#define HDIM 1024
#define H2   2048

#define SA 40              // smem row stride in halves (80B) -> conflict-free fragments
#define KC 32              // K-chunk (halves)
#define NC1 (DDIM / KC)    // 16 chunks for fc1
#define NC2 (HDIM / KC)    // 32 chunks for fc2

// -------- scratch --------
__device__ int    g_cnt[NEXP];
__device__ int    g_tok[NEXP * NTOK];
__device__ float  g_wt [NEXP * NTOK];
__device__ __half g_act[(size_t)NEXP * NTOK * HDIM];   // fp16 activations (~67MB)

// ===================== helpers =====================
__device__ __forceinline__ void mma_f16(float* c, const uint32_t* a, uint32_t b0, uint32_t b1) {
    asm volatile(
        "mma.sync.aligned.m16n8k16.row.col.f32.f16.f16.f32 "
        "{%0,%1,%2,%3}, {%4,%5,%6,%7}, {%8,%9}, {%0,%1,%2,%3};"
        : "+f"(c[0]), "+f"(c[1]), "+f"(c[2]), "+f"(c[3])
        : "r"(a[0]), "r"(a[1]), "r"(a[2]), "r"(a[3]), "r"(b0), "r"(b1));
}
// load 16 fp32, convert to 16 fp16 packed in two uint4
__device__ __forceinline__ void ld_cvt16(const float* p, uint4& lo, uint4& hi) {
    float4 v0 = ((const float4*)p)[0];
    float4 v1 = ((const float4*)p)[1];
    float4 v2 = ((const float4*)p)[2];
    float4 v3 = ((const float4*)p)[3];
    __half2 h0 = __floats2half2_rn(v0.x, v0.y), h1 = __floats2half2_rn(v0.z, v0.w);
    __half2 h2 = __floats2half2_rn(v1.x, v1.y), h3 = __floats2half2_rn(v1.z, v1.w);
    __half2 h4 = __floats2half2_rn(v2.x, v2.y), h5 = __floats2half2_rn(v2.z, v2.w);
    __half2 h6 = __floats2half2_rn(v3.x, v3.y), h7 = __floats2half2_rn(v3.z, v3.w);
    lo.x = *(uint32_t*)&h0; lo.y = *(uint32_t*)&h1; lo.z = *(uint32_t*)&h2; lo.w = *(uint32_t*)&h3;
    hi.x = *(uint32_t*)&h4; hi.y = *(uint32_t*)&h5; hi.z = *(uint32_t*)&h6; hi.w = *(uint32_t*)&h7;
}

// fp16 GEMM chunk: warp tile 32x64, K=32 (2 ksteps of k16). acc[2][8][4] fp32.
#define GEMM_CHUNK_H(A, B, wm, wn, lane, acc)                                  \
    _Pragma("unroll")                                                          \
    for (int ks = 0; ks < 2; ks++) {                                           \
        int ko = ks * 16 + 2 * ((lane) & 3);                                   \
        uint32_t afr[2][4];                                                    \
        _Pragma("unroll")                                                      \
        for (int mt = 0; mt < 2; mt++) {                                       \
            int r = (wm) + mt * 16 + ((lane) >> 2);                            \
            afr[mt][0] = *(const uint32_t*)&(A)[r * SA + ko];                  \
            afr[mt][1] = *(const uint32_t*)&(A)[(r + 8) * SA + ko];            \
            afr[mt][2] = *(const uint32_t*)&(A)[r * SA + ko + 8];              \
            afr[mt][3] = *(const uint32_t*)&(A)[(r + 8) * SA + ko + 8];        \
        }                                                                      \
        _Pragma("unroll")                                                      \
        for (int nt = 0; nt < 8; nt++) {                                       \
            int rn = (wn) + nt * 8 + ((lane) >> 2);                            \
            uint32_t b0 = *(const uint32_t*)&(B)[rn * SA + ko];                \
            uint32_t b1 = *(const uint32_t*)&(B)[rn * SA + ko + 8];            \
            mma_f16(acc[0][nt], afr[0], b0, b1);                               \
            mma_f16(acc[1][nt], afr[1], b0, b1);                               \
        }                                                                      \
    }

// =============================== zero ===============================
__global__ void k_zero(float* __restrict__ out) {
    int i = blockIdx.x * blockDim.x + threadIdx.x;
    if (i < NTOK * DDIM) out[i] = 0.f;
    if (i < NEXP) g_cnt[i] = 0;
}

// =============================== router (fp32 exact) ===============================
__global__ __launch_bounds__(256) void k_router(const float* __restrict__ x,
                                                const float* __restrict__ rw,
                                                const float* __restrict__ rb) {
    int tok  = blockIdx.x * 8 + (threadIdx.x >> 5);
    int lane = threadIdx.x & 31;
    if (tok >= NTOK) return;
    const float* xr = x + (size_t)tok * DDIM;
    float acc[NEXP];
#pragma unroll
    for (int e = 0; e < NEXP; e++) acc[e] = 0.f;
    for (int i = lane; i < DDIM; i += 32) {
        float xv = xr[i];
#pragma unroll
        for (int e = 0; e < NEXP; e++) acc[e] += xv * rw[e * DDIM + i];
    }
#pragma unroll
    for (int e = 0; e < NEXP; e++) {
#pragma unroll
        for (int o = 16; o > 0; o >>= 1)
            acc[e] += __shfl_xor_sync(0xffffffffu, acc[e], o);
    }
    if (lane == 0) {
        float lg[NEXP];
#pragma unroll
        for (int e = 0; e < NEXP; e++) lg[e] = acc[e] + rb[e];
        int i0 = 0; float v0 = lg[0];
#pragma unroll
        for (int e = 1; e < NEXP; e++) if (lg[e] > v0) { v0 = lg[e]; i0 = e; }
        int i1 = -1; float v1 = -3.0e38f;
#pragma unroll
        for (int e = 0; e < NEXP; e++) if (e != i0 && lg[e] > v1) { v1 = lg[e]; i1 = e; }
        float t  = __expf(v1 - v0);
        float w0 = 1.f / (1.f + t);
        float w1 = 1.f - w0;
        int s0 = atomicAdd(&g_cnt[i0], 1);
        g_tok[i0 * NTOK + s0] = tok;  g_wt[i0 * NTOK + s0] = w0;
        int s1 = atomicAdd(&g_cnt[i1], 1);
        g_tok[i1 * NTOK + s1] = tok;  g_wt[i1 * NTOK + s1] = w1;
    }
}

// =============================== fc1: fp16 mma + SwiGLU ===============================
// Block tile: 128 tokens x 128 cols (64 h1/h2 pairs, rows interleaved even=h1 odd=h2).
// grid = (HDIM/64, NTOK/128, NEXP), 256 threads = 8 warps (4m x 2n), warp tile 32x64.
__global__ __launch_bounds__(256, 2) void k_fc1(const float* __restrict__ x,
                                                const float* __restrict__ w1,
                                                const float* __restrict__ b1) {
    int e   = blockIdx.z;
    int cnt = g_cnt[e];
    int m0  = blockIdx.y * 128;
    if (m0 >= cnt) return;
    int c0  = blockIdx.x * 64;   // pair base

    __shared__ __half Asm[2 * 128 * SA];
    __shared__ __half Bsm[2 * 128 * SA];
    __shared__ int s_tok[128];

    int tid = threadIdx.x, wid = tid >> 5, lane = tid & 31;
    if (tid < 128) {
        int m = m0 + tid;
        s_tok[tid] = (m < cnt) ? g_tok[e * NTOK + m] : 0;
    }
    __syncthreads();

    // staging: each tile is 128 rows x 32 halves; 256 thr -> 16 halves each
    int arow = tid >> 1, aq = (tid & 1) * 16;
    const float* ap = x + (size_t)s_tok[arow] * DDIM + aq;
    int brow = tid >> 1, bq = (tid & 1) * 16;
    int pj   = brow >> 1;
    int w1row = (brow & 1) ? (HDIM + c0 + pj) : (c0 + pj);
    const float* bp = w1 + ((size_t)e * H2 + w1row) * DDIM + bq;

    int wm = (wid >> 1) * 32;
    int wn = (wid & 1) * 64;
    float acc[2][8][4] = {};

    uint4 alo, ahi, blo, bhi;
    ld_cvt16(ap, alo, ahi);
    ld_cvt16(bp, blo, bhi);
    {
        uint4* a_st = (uint4*)&Asm[arow * SA + aq];
        uint4* b_st = (uint4*)&Bsm[brow * SA + bq];
        a_st[0] = alo; *(uint4*)&Asm[arow * SA + aq + 8] = ahi;
        b_st[0] = blo; *(uint4*)&Bsm[brow * SA + bq + 8] = bhi;
    }
    __syncthreads();

    for (int c = 0; c < NC1; c++) {
        int s = c & 1;
        if (c + 1 < NC1) {
            int k0 = (c + 1) * KC;
            ld_cvt16(ap + k0, alo, ahi);
            ld_cvt16(bp + k0, blo, bhi);
        }
        const __half* A = Asm + s * 128 * SA;
        const __half* B = Bsm + s * 128 * SA;
        GEMM_CHUNK_H(A, B, wm, wn, lane, acc)
        if (c + 1 < NC1) {
            int s2 = (c + 1) & 1;
            *(uint4*)&Asm[s2 * 128 * SA + arow * SA + aq]     = alo;
            *(uint4*)&Asm[s2 * 128 * SA + arow * SA + aq + 8] = ahi;
            *(uint4*)&Bsm[s2 * 128 * SA + brow * SA + bq]     = blo;
            *(uint4*)&Bsm[s2 * 128 * SA + brow * SA + bq + 8] = bhi;
        }
        __syncthreads();
    }

    // epilogue: acc col pairs (even,odd) = (h1,h2); write fp16 activations
    const float* bb = b1 + (size_t)e * H2;
#pragma unroll
    for (int mt = 0; mt < 2; mt++) {
        int r_lo = m0 + wm + mt * 16 + (lane >> 2);
#pragma unroll
        for (int nt = 0; nt < 8; nt++) {
            int p = (wn >> 1) + nt * 4 + (lane & 3);   // pair index within 64
            int hcol = c0 + p;
            float bh1 = bb[hcol];
            float bh2 = bb[HDIM + hcol];
            if (r_lo < cnt) {
                float h1 = acc[mt][nt][0] + bh1;
                float h2 = acc[mt][nt][1] + bh2;
                g_act[((size_t)e * NTOK + r_lo) * HDIM + hcol] =
                    __float2half_rn((h1 / (1.f + __expf(-h1))) * h2);
            }
            int r_hi = r_lo + 8;
            if (r_hi < cnt) {
                float h1 = acc[mt][nt][2] + bh1;
                float h2 = acc[mt][nt][3] + bh2;
                g_act[((size_t)e * NTOK + r_hi) * HDIM + hcol] =
                    __float2half_rn((h1 / (1.f + __expf(-h1))) * h2);
            }
        }
    }
}

// =============================== fc2: fp16 mma + weighted combine ===============================
// Block tile: 128 tokens x 128 d-outputs. grid = (DDIM/128, NTOK/128, NEXP).
__global__ __launch_bounds__(256, 2) void k_fc2(const float* __restrict__ w2,
                                                const float* __restrict__ b2,
                                                float* __restrict__ out) {
    int e   = blockIdx.z;
    int cnt = g_cnt[e];
    int m0  = blockIdx.y * 128;
    if (m0 >= cnt) return;
    int n0  = blockIdx.x * 128;

    __shared__ __half Asm[2 * 128 * SA];
    __shared__ __half Bsm[2 * 128 * SA];
    __shared__ int   s_tok[128];
    __shared__ float s_wt[128];

    int tid = threadIdx.x, wid = tid >> 5, lane = tid & 31;
    if (tid < 128) {
        int m = m0 + tid;
        if (m < cnt) { s_tok[tid] = g_tok[e * NTOK + m]; s_wt[tid] = g_wt[e * NTOK + m]; }
        else         { s_tok[tid] = 0;                   s_wt[tid] = 0.f; }
    }
    __syncthreads();

    int arow = tid >> 1, aq = (tid & 1) * 16;
    const __half* ap = g_act + ((size_t)e * NTOK + m0 + arow) * HDIM + aq;
    int brow = tid >> 1, bq = (tid & 1) * 16;
    const float* bp = w2 + ((size_t)e * DDIM + n0 + brow) * HDIM + bq;

    int wm = (wid >> 1) * 32;
    int wn = (wid & 1) * 64;
    float acc[2][8][4] = {};

    uint4 alo, ahi, blo, bhi;
    alo = ((const uint4*)ap)[0]; ahi = ((const uint4*)ap)[1];
    ld_cvt16(bp, blo, bhi);
    *(uint4*)&Asm[arow * SA + aq]     = alo;
    *(uint4*)&Asm[arow * SA + aq + 8] = ahi;
    *(uint4*)&Bsm[brow * SA + bq]     = blo;
    *(uint4*)&Bsm[brow * SA + bq + 8] = bhi;
    __syncthreads();

    for (int c = 0; c < NC2; c++) {
        int s = c & 1;
        if (c + 1 < NC2) {
            int k0 = (c + 1) * KC;
            alo = ((const uint4*)(ap + k0))[0]; ahi = ((const uint4*)(ap + k0))[1];
            ld_cvt16(bp + k0, blo, bhi);
        }
        const __half* A = Asm + s * 128 * SA;
        const __half* B = Bsm + s * 128 * SA;
        GEMM_CHUNK_H(A, B, wm, wn, lane, acc)
        if (c + 1 < NC2) {
            int s2 = (c + 1) & 1;
            *(uint4*)&Asm[s2 * 128 * SA + arow * SA + aq]     = alo;
            *(uint4*)&Asm[s2 * 128 * SA + arow * SA + aq + 8] = ahi;
            *(uint4*)&Bsm[s2 * 128 * SA + brow * SA + bq]     = blo;
            *(uint4*)&Bsm[s2 * 128 * SA + brow * SA + bq + 8] = bhi;
        }
        __syncthreads();
    }

    const float* bb = b2 + (size_t)e * DDIM;
#pragma unroll
    for (int mt = 0; mt < 2; mt++) {
        int r_lo = wm + mt * 16 + (lane >> 2);
#pragma unroll
        for (int nt = 0; nt < 8; nt++) {
            int n_e = n0 + wn + nt * 8 + 2 * (lane & 3);
            float be = bb[n_e];
            float bo = bb[n_e + 1];
            if (m0 + r_lo < cnt) {
                int tok = s_tok[r_lo]; float wt = s_wt[r_lo];
                atomicAdd(&out[(size_t)tok * DDIM + n_e],     (acc[mt][nt][0] + be) * wt);
                atomicAdd(&out[(size_t)tok * DDIM + n_e + 1], (acc[mt][nt][1] + bo) * wt);
            }
            int r_hi = r_lo + 8;
            if (m0 + r_hi < cnt) {
                int tok = s_tok[r_hi]; float wt = s_wt[r_hi];
                atomicAdd(&out[(size_t)tok * DDIM + n_e],     (acc[mt][nt][2] + be) * wt);
                atomicAdd(&out[(size_t)tok * DDIM + n_e + 1], (acc[mt][nt][3] + bo) * wt);
            }
        }
    }
}

// =============================== launch ===============================
extern "C" void kernel_launch(void* const* d_in, const int* in_sizes, int n_in,
                              void* d_out, int out_size) {
    const float* x   = (const float*)d_in[0];
    const float* rw  = (const float*)d_in[1];
    const float* rb  = (const float*)d_in[2];
    const float* f1w = (const float*)d_in[3];
    const float* f1b = (const float*)d_in[4];
    const float* f2w = (const float*)d_in[5];
    const float* f2b = (const float*)d_in[6];
    float* out = (float*)d_out;

    k_zero<<<(NTOK * DDIM + 255) / 256, 256>>>(out);
    k_router<<<NTOK / 8, 256>>>(x, rw, rb);
    k_fc1<<<dim3(HDIM / 64, NTOK / 128, NEXP), 256>>>(x, f1w, f1b);
    k_fc2<<<dim3(DDIM / 128, NTOK / 128, NEXP), 256>>>(f2w, f2b, out);
}

// round 6
// speedup vs baseline: 4.1462x; 1.0011x over previous
#include <cuda_runtime.h>
#include <cuda_fp16.h>
#include <cstdint>

#define NTOK 4096
#define DDIM 512
#define NEXP 8
#define HDIM 1024
#define H2   2048

#define SA 40              // smem row stride in halves (80B) -> conflict-free fragments
#define KC 32              // K-chunk (halves)
#define NC1 (DDIM / KC)    // 16 chunks for fc1
#define NC2 (HDIM / KC)    // 32 chunks for fc2

// -------- scratch --------
__device__ int    g_cnt[NEXP];
__device__ int    g_tok[NEXP * NTOK];
__device__ float  g_wt [NEXP * NTOK];
__device__ __half g_act[(size_t)NEXP * NTOK * HDIM];   // fp16 activations (~67MB)

// ===================== helpers =====================
__device__ __forceinline__ void mma_f16(float* c, const uint32_t* a, uint32_t b0, uint32_t b1) {
    asm volatile(
        "mma.sync.aligned.m16n8k16.row.col.f32.f16.f16.f32 "
        "{%0,%1,%2,%3}, {%4,%5,%6,%7}, {%8,%9}, {%0,%1,%2,%3};"
        : "+f"(c[0]), "+f"(c[1]), "+f"(c[2]), "+f"(c[3])
        : "r"(a[0]), "r"(a[1]), "r"(a[2]), "r"(a[3]), "r"(b0), "r"(b1));
}
// load 16 fp32, convert to 16 fp16 packed in two uint4
__device__ __forceinline__ void ld_cvt16(const float* p, uint4& lo, uint4& hi) {
    float4 v0 = ((const float4*)p)[0];
    float4 v1 = ((const float4*)p)[1];
    float4 v2 = ((const float4*)p)[2];
    float4 v3 = ((const float4*)p)[3];
    __half2 h0 = __floats2half2_rn(v0.x, v0.y), h1 = __floats2half2_rn(v0.z, v0.w);
    __half2 h2 = __floats2half2_rn(v1.x, v1.y), h3 = __floats2half2_rn(v1.z, v1.w);
    __half2 h4 = __floats2half2_rn(v2.x, v2.y), h5 = __floats2half2_rn(v2.z, v2.w);
    __half2 h6 = __floats2half2_rn(v3.x, v3.y), h7 = __floats2half2_rn(v3.z, v3.w);
    lo.x = *(uint32_t*)&h0; lo.y = *(uint32_t*)&h1; lo.z = *(uint32_t*)&h2; lo.w = *(uint32_t*)&h3;
    hi.x = *(uint32_t*)&h4; hi.y = *(uint32_t*)&h5; hi.z = *(uint32_t*)&h6; hi.w = *(uint32_t*)&h7;
}

// fp16 GEMM chunk: warp tile 32x64, K=32 (2 ksteps of k16). acc[2][8][4] fp32.
#define GEMM_CHUNK_H(A, B, wm, wn, lane, acc)                                  \
    _Pragma("unroll")                                                          \
    for (int ks = 0; ks < 2; ks++) {                                           \
        int ko = ks * 16 + 2 * ((lane) & 3);                                   \
        uint32_t afr[2][4];                                                    \
        _Pragma("unroll")                                                      \
        for (int mt = 0; mt < 2; mt++) {                                       \
            int r = (wm) + mt * 16 + ((lane) >> 2);                            \
            afr[mt][0] = *(const uint32_t*)&(A)[r * SA + ko];                  \
            afr[mt][1] = *(const uint32_t*)&(A)[(r + 8) * SA + ko];            \
            afr[mt][2] = *(const uint32_t*)&(A)[r * SA + ko + 8];              \
            afr[mt][3] = *(const uint32_t*)&(A)[(r + 8) * SA + ko + 8];        \
        }                                                                      \
        _Pragma("unroll")                                                      \
        for (int nt = 0; nt < 8; nt++) {                                       \
            int rn = (wn) + nt * 8 + ((lane) >> 2);                            \
            uint32_t b0 = *(const uint32_t*)&(B)[rn * SA + ko];                \
            uint32_t b1 = *(const uint32_t*)&(B)[rn * SA + ko + 8];            \
            mma_f16(acc[0][nt], afr[0], b0, b1);                               \
            mma_f16(acc[1][nt], afr[1], b0, b1);                               \
        }                                                                      \
    }

// =============================== zero ===============================
__global__ void k_zero(float* __restrict__ out) {
    int i = blockIdx.x * blockDim.x + threadIdx.x;
    if (i < NTOK * DDIM) out[i] = 0.f;
    if (i < NEXP) g_cnt[i] = 0;
}

// =============================== router (fp32 exact) ===============================
__global__ __launch_bounds__(256) void k_router(const float* __restrict__ x,
                                                const float* __restrict__ rw,
                                                const float* __restrict__ rb) {
    int tok  = blockIdx.x * 8 + (threadIdx.x >> 5);
    int lane = threadIdx.x & 31;
    if (tok >= NTOK) return;
    const float* xr = x + (size_t)tok * DDIM;
    float acc[NEXP];
#pragma unroll
    for (int e = 0; e < NEXP; e++) acc[e] = 0.f;
    for (int i = lane; i < DDIM; i += 32) {
        float xv = xr[i];
#pragma unroll
        for (int e = 0; e < NEXP; e++) acc[e] += xv * rw[e * DDIM + i];
    }
#pragma unroll
    for (int e = 0; e < NEXP; e++) {
#pragma unroll
        for (int o = 16; o > 0; o >>= 1)
            acc[e] += __shfl_xor_sync(0xffffffffu, acc[e], o);
    }
    if (lane == 0) {
        float lg[NEXP];
#pragma unroll
        for (int e = 0; e < NEXP; e++) lg[e] = acc[e] + rb[e];
        int i0 = 0; float v0 = lg[0];
#pragma unroll
        for (int e = 1; e < NEXP; e++) if (lg[e] > v0) { v0 = lg[e]; i0 = e; }
        int i1 = -1; float v1 = -3.0e38f;
#pragma unroll
        for (int e = 0; e < NEXP; e++) if (e != i0 && lg[e] > v1) { v1 = lg[e]; i1 = e; }
        float t  = __expf(v1 - v0);
        float w0 = 1.f / (1.f + t);
        float w1 = 1.f - w0;
        int s0 = atomicAdd(&g_cnt[i0], 1);
        g_tok[i0 * NTOK + s0] = tok;  g_wt[i0 * NTOK + s0] = w0;
        int s1 = atomicAdd(&g_cnt[i1], 1);
        g_tok[i1 * NTOK + s1] = tok;  g_wt[i1 * NTOK + s1] = w1;
    }
}

// =============================== fc1: fp16 mma + SwiGLU ===============================
// Block tile: 128 tokens x 128 cols (64 h1/h2 pairs, rows interleaved even=h1 odd=h2).
// grid = (HDIM/64, NTOK/128, NEXP), 256 threads = 8 warps (4m x 2n), warp tile 32x64.
__global__ __launch_bounds__(256, 2) void k_fc1(const float* __restrict__ x,
                                                const float* __restrict__ w1,
                                                const float* __restrict__ b1) {
    int e   = blockIdx.z;
    int cnt = g_cnt[e];
    int m0  = blockIdx.y * 128;
    if (m0 >= cnt) return;
    int c0  = blockIdx.x * 64;   // pair base

    __shared__ __half Asm[2 * 128 * SA];
    __shared__ __half Bsm[2 * 128 * SA];
    __shared__ int s_tok[128];

    int tid = threadIdx.x, wid = tid >> 5, lane = tid & 31;
    if (tid < 128) {
        int m = m0 + tid;
        s_tok[tid] = (m < cnt) ? g_tok[e * NTOK + m] : 0;
    }
    __syncthreads();

    // staging: each tile is 128 rows x 32 halves; 256 thr -> 16 halves each
    int arow = tid >> 1, aq = (tid & 1) * 16;
    const float* ap = x + (size_t)s_tok[arow] * DDIM + aq;
    int brow = tid >> 1, bq = (tid & 1) * 16;
    int pj   = brow >> 1;
    int w1row = (brow & 1) ? (HDIM + c0 + pj) : (c0 + pj);
    const float* bp = w1 + ((size_t)e * H2 + w1row) * DDIM + bq;

    int wm = (wid >> 1) * 32;
    int wn = (wid & 1) * 64;
    float acc[2][8][4] = {};

    uint4 alo, ahi, blo, bhi;
    ld_cvt16(ap, alo, ahi);
    ld_cvt16(bp, blo, bhi);
    {
        uint4* a_st = (uint4*)&Asm[arow * SA + aq];
        uint4* b_st = (uint4*)&Bsm[brow * SA + bq];
        a_st[0] = alo; *(uint4*)&Asm[arow * SA + aq + 8] = ahi;
        b_st[0] = blo; *(uint4*)&Bsm[brow * SA + bq + 8] = bhi;
    }
    __syncthreads();

    for (int c = 0; c < NC1; c++) {
        int s = c & 1;
        if (c + 1 < NC1) {
            int k0 = (c + 1) * KC;
            ld_cvt16(ap + k0, alo, ahi);
            ld_cvt16(bp + k0, blo, bhi);
        }
        const __half* A = Asm + s * 128 * SA;
        const __half* B = Bsm + s * 128 * SA;
        GEMM_CHUNK_H(A, B, wm, wn, lane, acc)
        if (c + 1 < NC1) {
            int s2 = (c + 1) & 1;
            *(uint4*)&Asm[s2 * 128 * SA + arow * SA + aq]     = alo;
            *(uint4*)&Asm[s2 * 128 * SA + arow * SA + aq + 8] = ahi;
            *(uint4*)&Bsm[s2 * 128 * SA + brow * SA + bq]     = blo;
            *(uint4*)&Bsm[s2 * 128 * SA + brow * SA + bq + 8] = bhi;
        }
        __syncthreads();
    }

    // epilogue: acc col pairs (even,odd) = (h1,h2); write fp16 activations
    const float* bb = b1 + (size_t)e * H2;
#pragma unroll
    for (int mt = 0; mt < 2; mt++) {
        int r_lo = m0 + wm + mt * 16 + (lane >> 2);
#pragma unroll
        for (int nt = 0; nt < 8; nt++) {
            int p = (wn >> 1) + nt * 4 + (lane & 3);   // pair index within 64
            int hcol = c0 + p;
            float bh1 = bb[hcol];
            float bh2 = bb[HDIM + hcol];
            if (r_lo < cnt) {
                float h1 = acc[mt][nt][0] + bh1;
                float h2 = acc[mt][nt][1] + bh2;
                g_act[((size_t)e * NTOK + r_lo) * HDIM + hcol] =
                    __float2half_rn((h1 / (1.f + __expf(-h1))) * h2);
            }
            int r_hi = r_lo + 8;
            if (r_hi < cnt) {
                float h1 = acc[mt][nt][2] + bh1;
                float h2 = acc[mt][nt][3] + bh2;
                g_act[((size_t)e * NTOK + r_hi) * HDIM + hcol] =
                    __float2half_rn((h1 / (1.f + __expf(-h1))) * h2);
            }
        }
    }
}

// =============================== fc2: fp16 mma + weighted combine ===============================
// Block tile: 128 tokens x 128 d-outputs. grid = (DDIM/128, NTOK/128, NEXP).
__global__ __launch_bounds__(256, 2) void k_fc2(const float* __restrict__ w2,
                                                const float* __restrict__ b2,
                                                float* __restrict__ out) {
    int e   = blockIdx.z;
    int cnt = g_cnt[e];
    int m0  = blockIdx.y * 128;
    if (m0 >= cnt) return;
    int n0  = blockIdx.x * 128;

    __shared__ __half Asm[2 * 128 * SA];
    __shared__ __half Bsm[2 * 128 * SA];
    __shared__ int   s_tok[128];
    __shared__ float s_wt[128];

    int tid = threadIdx.x, wid = tid >> 5, lane = tid & 31;
    if (tid < 128) {
        int m = m0 + tid;
        if (m < cnt) { s_tok[tid] = g_tok[e * NTOK + m]; s_wt[tid] = g_wt[e * NTOK + m]; }
        else         { s_tok[tid] = 0;                   s_wt[tid] = 0.f; }
    }
    __syncthreads();

    int arow = tid >> 1, aq = (tid & 1) * 16;
    const __half* ap = g_act + ((size_t)e * NTOK + m0 + arow) * HDIM + aq;
    int brow = tid >> 1, bq = (tid & 1) * 16;
    const float* bp = w2 + ((size_t)e * DDIM + n0 + brow) * HDIM + bq;

    int wm = (wid >> 1) * 32;
    int wn = (wid & 1) * 64;
    float acc[2][8][4] = {};

    uint4 alo, ahi, blo, bhi;
    alo = ((const uint4*)ap)[0]; ahi = ((const uint4*)ap)[1];
    ld_cvt16(bp, blo, bhi);
    *(uint4*)&Asm[arow * SA + aq]     = alo;
    *(uint4*)&Asm[arow * SA + aq + 8] = ahi;
    *(uint4*)&Bsm[brow * SA + bq]     = blo;
    *(uint4*)&Bsm[brow * SA + bq + 8] = bhi;
    __syncthreads();

    for (int c = 0; c < NC2; c++) {
        int s = c & 1;
        if (c + 1 < NC2) {
            int k0 = (c + 1) * KC;
            alo = ((const uint4*)(ap + k0))[0]; ahi = ((const uint4*)(ap + k0))[1];
            ld_cvt16(bp + k0, blo, bhi);
        }
        const __half* A = Asm + s * 128 * SA;
        const __half* B = Bsm + s * 128 * SA;
        GEMM_CHUNK_H(A, B, wm, wn, lane, acc)
        if (c + 1 < NC2) {
            int s2 = (c + 1) & 1;
            *(uint4*)&Asm[s2 * 128 * SA + arow * SA + aq]     = alo;
            *(uint4*)&Asm[s2 * 128 * SA + arow * SA + aq + 8] = ahi;
            *(uint4*)&Bsm[s2 * 128 * SA + brow * SA + bq]     = blo;
            *(uint4*)&Bsm[s2 * 128 * SA + brow * SA + bq + 8] = bhi;
        }
        __syncthreads();
    }

    const float* bb = b2 + (size_t)e * DDIM;
#pragma unroll
    for (int mt = 0; mt < 2; mt++) {
        int r_lo = wm + mt * 16 + (lane >> 2);
#pragma unroll
        for (int nt = 0; nt < 8; nt++) {
            int n_e = n0 + wn + nt * 8 + 2 * (lane & 3);
            float be = bb[n_e];
            float bo = bb[n_e + 1];
            if (m0 + r_lo < cnt) {
                int tok = s_tok[r_lo]; float wt = s_wt[r_lo];
                atomicAdd(&out[(size_t)tok * DDIM + n_e],     (acc[mt][nt][0] + be) * wt);
                atomicAdd(&out[(size_t)tok * DDIM + n_e + 1], (acc[mt][nt][1] + bo) * wt);
            }
            int r_hi = r_lo + 8;
            if (m0 + r_hi < cnt) {
                int tok = s_tok[r_hi]; float wt = s_wt[r_hi];
                atomicAdd(&out[(size_t)tok * DDIM + n_e],     (acc[mt][nt][2] + be) * wt);
                atomicAdd(&out[(size_t)tok * DDIM + n_e + 1], (acc[mt][nt][3] + bo) * wt);
            }
        }
    }
}

// =============================== launch ===============================
extern "C" void kernel_launch(void* const* d_in, const int* in_sizes, int n_in,
                              void* d_out, int out_size) {
    const float* x   = (const float*)d_in[0];
    const float* rw  = (const float*)d_in[1];
    const float* rb  = (const float*)d_in[2];
    const float* f1w = (const float*)d_in[3];
    const float* f1b = (const float*)d_in[4];
    const float* f2w = (const float*)d_in[5];
    const float* f2b = (const float*)d_in[6];
    float* out = (float*)d_out;

    k_zero<<<(NTOK * DDIM + 255) / 256, 256>>>(out);
    k_router<<<NTOK / 8, 256>>>(x, rw, rb);
    k_fc1<<<dim3(HDIM / 64, NTOK / 128, NEXP), 256>>>(x, f1w, f1b);
    k_fc2<<<dim3(DDIM / 128, NTOK / 128, NEXP), 256>>>(f2w, f2b, out);
}

// round 7
// speedup vs baseline: 5.5745x; 1.3445x over previous
#include <cuda_runtime.h>
#include <cuda_fp16.h>
#include <cstdint>

#define NTOK 4096
#define DDIM 512
#define NEXP 8
#define HDIM 1024
#define H2   2048

#define CH   64                 // K-chunk in halves = 128B rows
#define NCH1 (DDIM / CH)        // 8 chunks (fc1)
#define NCH2 (HDIM / CH)        // 16 chunks (fc2)
#define STAGE_BYTES 32768       // A tile 16KB + B tile 16KB
#define SMEM_DYN (3 * STAGE_BYTES + 2048)

// -------- scratch (device globals; no allocation allowed) --------
__device__ int    g_cnt[NEXP];
__device__ int    g_tok[NEXP * NTOK];
__device__ float  g_wt [NEXP * NTOK];
__device__ __half g_act[(size_t)NEXP * NTOK * HDIM];   // fp16 activations
__device__ __half g_xh [(size_t)NTOK * DDIM];          // fp16 x
__device__ __half g_w1h[(size_t)NEXP * H2 * DDIM];     // fp16 w1, rows interleaved: 2p=h1[p], 2p+1=h2[p]
__device__ __half g_w2h[(size_t)NEXP * DDIM * HDIM];   // fp16 w2

// ===================== helpers =====================
__device__ __forceinline__ uint32_t smem_u32(const void* p) {
    uint32_t a;
    asm("{ .reg .u64 t; cvta.to.shared.u64 t, %1; cvt.u32.u64 %0, t; }" : "=r"(a) : "l"(p));
    return a;
}
__device__ __forceinline__ uint32_t swz(uint32_t o) { return o ^ ((o >> 3) & 0x70); }

#define CP16(dst, src) asm volatile("cp.async.cg.shared.global [%0], [%1], 16;" :: "r"(dst), "l"(src) : "memory")
#define CPCOMMIT()     asm volatile("cp.async.commit_group;" ::: "memory")
#define CPWAIT1()      asm volatile("cp.async.wait_group 1;" ::: "memory")

__device__ __forceinline__ void ldsm4(uint32_t& r0, uint32_t& r1, uint32_t& r2, uint32_t& r3,
                                      uint32_t addr) {
    asm volatile("ldmatrix.sync.aligned.m8n8.x4.shared.b16 {%0,%1,%2,%3}, [%4];"
                 : "=r"(r0), "=r"(r1), "=r"(r2), "=r"(r3) : "r"(addr));
}
__device__ __forceinline__ void mma_f16(float* c, const uint32_t* a, uint32_t b0, uint32_t b1) {
    asm volatile(
        "mma.sync.aligned.m16n8k16.row.col.f32.f16.f16.f32 "
        "{%0,%1,%2,%3}, {%4,%5,%6,%7}, {%8,%9}, {%0,%1,%2,%3};"
        : "+f"(c[0]), "+f"(c[1]), "+f"(c[2]), "+f"(c[3])
        : "r"(a[0]), "r"(a[1]), "r"(a[2]), "r"(a[3]), "r"(b0), "r"(b1));
}
__device__ __forceinline__ uint4 pack8(const float* p) {
    float4 a = ((const float4*)p)[0], b = ((const float4*)p)[1];
    __half2 h0 = __floats2half2_rn(a.x, a.y), h1 = __floats2half2_rn(a.z, a.w);
    __half2 h2 = __floats2half2_rn(b.x, b.y), h3 = __floats2half2_rn(b.z, b.w);
    uint4 u;
    u.x = *(uint32_t*)&h0; u.y = *(uint32_t*)&h1;
    u.z = *(uint32_t*)&h2; u.w = *(uint32_t*)&h3;
    return u;
}

// GEMM over one K=64 chunk: 8 warps (4m x 2n), warp tile 32x64, acc[2][8][4] fp32.
__device__ __forceinline__ void gemm_k64(uint32_t Ab, uint32_t Bb, int wm, int wn,
                                         int lane, float acc[2][8][4]) {
    int lr = lane & 15;
    int hi = (lane >> 4) << 4;   // 0 or 16 bytes
#pragma unroll
    for (int ks = 0; ks < 4; ks++) {
        uint32_t afr[2][4];
#pragma unroll
        for (int mt = 0; mt < 2; mt++) {
            uint32_t off = (uint32_t)((wm + mt * 16 + lr) * 128 + ks * 32 + hi);
            ldsm4(afr[mt][0], afr[mt][1], afr[mt][2], afr[mt][3], Ab + swz(off));
        }
#pragma unroll
        for (int g = 0; g < 4; g++) {
            uint32_t b0, b1, b2, b3;
            uint32_t off = (uint32_t)((wn + g * 16 + lr) * 128 + ks * 32 + hi);
            ldsm4(b0, b1, b2, b3, Bb + swz(off));
            mma_f16(acc[0][2 * g],     afr[0], b0, b2);
            mma_f16(acc[1][2 * g],     afr[1], b0, b2);
            mma_f16(acc[0][2 * g + 1], afr[0], b1, b3);
            mma_f16(acc[1][2 * g + 1], afr[1], b1, b3);
        }
    }
}

// issue one chunk's A+B tiles: each thread moves 4x16B of A and 4x16B of B
__device__ __forceinline__ void issue_chunk(uint32_t Ab, uint32_t Bb,
                                            const __half* asrc, const __half* bsrc,
                                            uint32_t dstoff) {
#pragma unroll
    for (int s = 0; s < 4; s++) {
        CP16(Ab + swz(dstoff + 16 * s), asrc + 8 * s);
        CP16(Bb + swz(dstoff + 16 * s), bsrc + 8 * s);
    }
}

// =============================== zero ===============================
__global__ void k_zero(float* __restrict__ out) {
    int i = blockIdx.x * blockDim.x + threadIdx.x;
    if (i < NTOK * DDIM) out[i] = 0.f;
    if (i < NEXP) g_cnt[i] = 0;
}

// =============================== convert (x, w1 interleaved, w2) ===============================
#define NX8  (NTOK * DDIM / 8)            // 262144
#define NW18 (NEXP * H2 * DDIM / 8)       // 1048576
#define NW28 (NEXP * DDIM * HDIM / 8)     // 524288
__global__ __launch_bounds__(256) void k_cvt(const float* __restrict__ x,
                                             const float* __restrict__ w1,
                                             const float* __restrict__ w2) {
    int idx = blockIdx.x * blockDim.x + threadIdx.x;
    if (idx < NX8) {
        int o = idx * 8;
        ((uint4*)g_xh)[idx] = pack8(x + o);
    } else if (idx < NX8 + NW18) {
        int i2 = idx - NX8;
        int o  = i2 * 8;
        int orow = o >> 9;                 // 512 halves per row
        int k    = o & 511;
        int e = orow >> 11;
        int r = orow & 2047;
        const float* src = w1 + ((size_t)(e << 11) + ((r & 1) << 10) + (r >> 1)) * DDIM + k;
        ((uint4*)g_w1h)[i2] = pack8(src);
    } else if (idx < NX8 + NW18 + NW28) {
        int i3 = idx - NX8 - NW18;
        ((uint4*)g_w2h)[i3] = pack8(w2 + i3 * 8);
    }
}

// =============================== router (fp32 exact) ===============================
__global__ __launch_bounds__(256) void k_router(const float* __restrict__ x,
                                                const float* __restrict__ rw,
                                                const float* __restrict__ rb) {
    int tok  = blockIdx.x * 8 + (threadIdx.x >> 5);
    int lane = threadIdx.x & 31;
    if (tok >= NTOK) return;
    const float* xr = x + (size_t)tok * DDIM;
    float acc[NEXP];
#pragma unroll
    for (int e = 0; e < NEXP; e++) acc[e] = 0.f;
    for (int i = lane; i < DDIM; i += 32) {
        float xv = xr[i];
#pragma unroll
        for (int e = 0; e < NEXP; e++) acc[e] += xv * rw[e * DDIM + i];
    }
#pragma unroll
    for (int e = 0; e < NEXP; e++) {
#pragma unroll
        for (int o = 16; o > 0; o >>= 1)
            acc[e] += __shfl_xor_sync(0xffffffffu, acc[e], o);
    }
    if (lane == 0) {
        float lg[NEXP];
#pragma unroll
        for (int e = 0; e < NEXP; e++) lg[e] = acc[e] + rb[e];
        int i0 = 0; float v0 = lg[0];
#pragma unroll
        for (int e = 1; e < NEXP; e++) if (lg[e] > v0) { v0 = lg[e]; i0 = e; }
        int i1 = -1; float v1 = -3.0e38f;
#pragma unroll
        for (int e = 0; e < NEXP; e++) if (e != i0 && lg[e] > v1) { v1 = lg[e]; i1 = e; }
        float t  = __expf(v1 - v0);
        float w0 = 1.f / (1.f + t);
        float w1_ = 1.f - w0;
        int s0 = atomicAdd(&g_cnt[i0], 1);
        g_tok[i0 * NTOK + s0] = tok;  g_wt[i0 * NTOK + s0] = w0;
        int s1 = atomicAdd(&g_cnt[i1], 1);
        g_tok[i1 * NTOK + s1] = tok;  g_wt[i1 * NTOK + s1] = w1_;
    }
}

// =============================== fc1: async fp16 mma + SwiGLU ===============================
// Block tile: 128 tokens x 128 interleaved cols (64 pairs). grid=(HDIM/64, NTOK/128, NEXP).
__global__ __launch_bounds__(256, 2) void k_fc1(const float* __restrict__ b1) {
    int e   = blockIdx.z;
    int cnt = g_cnt[e];
    int m0  = blockIdx.y * 128;
    if (m0 >= cnt) return;
    int c0  = blockIdx.x * 64;   // pair base

    extern __shared__ char smem[];
    uint32_t sb    = smem_u32(smem);
    uint32_t tiles = (sb + 1023) & ~1023u;
    int* s_tok = (int*)(smem + (tiles - sb) + 3 * STAGE_BYTES);

    int tid = threadIdx.x, wid = tid >> 5, lane = tid & 31;
    if (tid < 128) {
        int m = m0 + tid;
        s_tok[tid] = (m < cnt) ? g_tok[e * NTOK + m] : 0;
    }
    __syncthreads();

    int ra = tid >> 1;
    uint32_t dstoff = (uint32_t)(ra * 128 + (tid & 1) * 64);
    const __half* asrc = g_xh + (size_t)s_tok[ra] * DDIM + (tid & 1) * 32;
    const __half* bsrc = g_w1h + ((size_t)e * H2 + 2 * c0 + ra) * DDIM + (tid & 1) * 32;

    int wm = (wid >> 1) * 32;
    int wn = (wid & 1) * 64;
    float acc[2][8][4] = {};

    // prologue: stages 0,1
#pragma unroll
    for (int c = 0; c < 2; c++) {
        uint32_t Ab = tiles + c * STAGE_BYTES, Bb = Ab + 16384;
        issue_chunk(Ab, Bb, asrc + c * CH, bsrc + c * CH, dstoff);
        CPCOMMIT();
    }

    for (int c = 0; c < NCH1; c++) {
        CPWAIT1();
        __syncthreads();
        if (c + 2 < NCH1) {
            int s2 = (c + 2) % 3;
            issue_chunk(tiles + s2 * STAGE_BYTES, tiles + s2 * STAGE_BYTES + 16384,
                        asrc + (c + 2) * CH, bsrc + (c + 2) * CH, dstoff);
        }
        CPCOMMIT();
        int s = c % 3;
        gemm_k64(tiles + s * STAGE_BYTES, tiles + s * STAGE_BYTES + 16384, wm, wn, lane, acc);
    }

    // epilogue: acc col pairs (even,odd) = (h1,h2); write fp16 activations
    const float* bb = b1 + (size_t)e * H2;
#pragma unroll
    for (int mt = 0; mt < 2; mt++) {
        int r_lo = m0 + wm + mt * 16 + (lane >> 2);
#pragma unroll
        for (int nt = 0; nt < 8; nt++) {
            int p = (wn >> 1) + nt * 4 + (lane & 3);
            int hcol = c0 + p;
            float bh1 = bb[hcol];
            float bh2 = bb[HDIM + hcol];
            if (r_lo < cnt) {
                float h1 = acc[mt][nt][0] + bh1;
                float h2 = acc[mt][nt][1] + bh2;
                g_act[((size_t)e * NTOK + r_lo) * HDIM + hcol] =
                    __float2half_rn((h1 / (1.f + __expf(-h1))) * h2);
            }
            int r_hi = r_lo + 8;
            if (r_hi < cnt) {
                float h1 = acc[mt][nt][2] + bh1;
                float h2 = acc[mt][nt][3] + bh2;
                g_act[((size_t)e * NTOK + r_hi) * HDIM + hcol] =
                    __float2half_rn((h1 / (1.f + __expf(-h1))) * h2);
            }
        }
    }
}

// =============================== fc2: async fp16 mma + weighted combine ===============================
// Block tile: 128 tokens x 128 d-outputs. grid=(DDIM/128, NTOK/128, NEXP).
__global__ __launch_bounds__(256, 2) void k_fc2(const float* __restrict__ b2,
                                                float* __restrict__ out) {
    int e   = blockIdx.z;
    int cnt = g_cnt[e];
    int m0  = blockIdx.y * 128;
    if (m0 >= cnt) return;
    int n0  = blockIdx.x * 128;

    extern __shared__ char smem[];
    uint32_t sb    = smem_u32(smem);
    uint32_t tiles = (sb + 1023) & ~1023u;
    int*   s_tok = (int*)(smem + (tiles - sb) + 3 * STAGE_BYTES);
    float* s_wt  = (float*)(smem + (tiles - sb) + 3 * STAGE_BYTES + 512);

    int tid = threadIdx.x, wid = tid >> 5, lane = tid & 31;
    if (tid < 128) {
        int m = m0 + tid;
        if (m < cnt) { s_tok[tid] = g_tok[e * NTOK + m]; s_wt[tid] = g_wt[e * NTOK + m]; }
        else         { s_tok[tid] = 0;                   s_wt[tid] = 0.f; }
    }
    __syncthreads();

    int ra = tid >> 1;
    uint32_t dstoff = (uint32_t)(ra * 128 + (tid & 1) * 64);
    const __half* asrc = g_act + ((size_t)e * NTOK + m0 + ra) * HDIM + (tid & 1) * 32;
    const __half* bsrc = g_w2h + ((size_t)e * DDIM + n0 + ra) * HDIM + (tid & 1) * 32;

    int wm = (wid >> 1) * 32;
    int wn = (wid & 1) * 64;
    float acc[2][8][4] = {};

#pragma unroll
    for (int c = 0; c < 2; c++) {
        uint32_t Ab = tiles + c * STAGE_BYTES, Bb = Ab + 16384;
        issue_chunk(Ab, Bb, asrc + c * CH, bsrc + c * CH, dstoff);
        CPCOMMIT();
    }

    for (int c = 0; c < NCH2; c++) {
        CPWAIT1();
        __syncthreads();
        if (c + 2 < NCH2) {
            int s2 = (c + 2) % 3;
            issue_chunk(tiles + s2 * STAGE_BYTES, tiles + s2 * STAGE_BYTES + 16384,
                        asrc + (c + 2) * CH, bsrc + (c + 2) * CH, dstoff);
        }
        CPCOMMIT();
        int s = c % 3;
        gemm_k64(tiles + s * STAGE_BYTES, tiles + s * STAGE_BYTES + 16384, wm, wn, lane, acc);
    }

    const float* bb = b2 + (size_t)e * DDIM;
#pragma unroll
    for (int mt = 0; mt < 2; mt++) {
        int r_lo = wm + mt * 16 + (lane >> 2);
#pragma unroll
        for (int nt = 0; nt < 8; nt++) {
            int n_e = n0 + wn + nt * 8 + 2 * (lane & 3);
            float be = bb[n_e];
            float bo = bb[n_e + 1];
            if (m0 + r_lo < cnt) {
                int tok = s_tok[r_lo]; float wt = s_wt[r_lo];
                atomicAdd(&out[(size_t)tok * DDIM + n_e],     (acc[mt][nt][0] + be) * wt);
                atomicAdd(&out[(size_t)tok * DDIM + n_e + 1], (acc[mt][nt][1] + bo) * wt);
            }
            int r_hi = r_lo + 8;
            if (m0 + r_hi < cnt) {
                int tok = s_tok[r_hi]; float wt = s_wt[r_hi];
                atomicAdd(&out[(size_t)tok * DDIM + n_e],     (acc[mt][nt][2] + be) * wt);
                atomicAdd(&out[(size_t)tok * DDIM + n_e + 1], (acc[mt][nt][3] + bo) * wt);
            }
        }
    }
}

// =============================== launch ===============================
extern "C" void kernel_launch(void* const* d_in, const int* in_sizes, int n_in,
                              void* d_out, int out_size) {
    const float* x   = (const float*)d_in[0];
    const float* rw  = (const float*)d_in[1];
    const float* rb  = (const float*)d_in[2];
    const float* f1w = (const float*)d_in[3];
    const float* f1b = (const float*)d_in[4];
    const float* f2w = (const float*)d_in[5];
    const float* f2b = (const float*)d_in[6];
    float* out = (float*)d_out;

    cudaFuncSetAttribute(k_fc1, cudaFuncAttributeMaxDynamicSharedMemorySize, SMEM_DYN);
    cudaFuncSetAttribute(k_fc2, cudaFuncAttributeMaxDynamicSharedMemorySize, SMEM_DYN);

    k_zero<<<(NTOK * DDIM + 255) / 256, 256>>>(out);
    k_cvt<<<(NX8 + NW18 + NW28 + 255) / 256, 256>>>(x, f1w, f2w);
    k_router<<<NTOK / 8, 256>>>(x, rw, rb);
    k_fc1<<<dim3(HDIM / 64, NTOK / 128, NEXP), 256, SMEM_DYN>>>(f1b);
    k_fc2<<<dim3(DDIM / 128, NTOK / 128, NEXP), 256, SMEM_DYN>>>(f2b, out);
}